// round 10
// baseline (speedup 1.0000x reference)
#include <cuda_runtime.h>
#include <cuda_fp16.h>
#include <cstdint>

#define NN 100000
#define NE 6400000
#define DIN 128
#define HID 16
#define TOT (NN * HID)
#define NB1 391            // ceil(NN/256)

// ---------------- scratch (static device globals; no allocation) ----------------
__device__ __align__(16) __half g_h1[TOT];   // fp16: dinv[n] * (xn @ W1)
__device__ __align__(16) __half g_t[TOT];    // fp16: dinv[n] * (dropout(relu(conv1)) @ W2)
__device__ float g_dinv[NN];
__device__ int   g_cnt[NN];                  // in-degree (excl self-loop); re-zeroed each replay
__device__ int   g_off[NN];                  // CSR row start
__device__ int   g_cur[NN];                  // fill cursor -> row end after fill
__device__ int   g_bsum[512];                // block sums for scan
__device__ int   g_csrc[NE];                 // CSR: src per slot

// ---------------- JAX Threefry-2x32 (20 rounds), bit-exact ----------------
__host__ __device__ __forceinline__ void threefry2x32(
    uint32_t k0, uint32_t k1, uint32_t x0, uint32_t x1,
    uint32_t& o0, uint32_t& o1)
{
    uint32_t ks2 = k0 ^ k1 ^ 0x1BD11BDAu;
    x0 += k0; x1 += k1;
#define TF_R(r) { x0 += x1; x1 = (x1 << r) | (x1 >> (32 - r)); x1 ^= x0; }
    TF_R(13) TF_R(15) TF_R(26) TF_R(6)
    x0 += k1;  x1 += ks2 + 1u;
    TF_R(17) TF_R(29) TF_R(16) TF_R(24)
    x0 += ks2; x1 += k0 + 2u;
    TF_R(13) TF_R(15) TF_R(26) TF_R(6)
    x0 += k0;  x1 += k1 + 3u;
    TF_R(17) TF_R(29) TF_R(16) TF_R(24)
    x0 += k1;  x1 += ks2 + 4u;
    TF_R(13) TF_R(15) TF_R(26) TF_R(6)
    x0 += ks2; x1 += k0 + 5u;
#undef TF_R
    o0 = x0; o1 = x1;
}

// Partitionable-mode random_bits: counter (0, i); output = o0 ^ o1.
__device__ __forceinline__ float dropout_elem(float h, uint32_t k0, uint32_t k1, uint32_t i)
{
    uint32_t o0, o1;
    threefry2x32(k0, k1, 0u, i, o0, o1);
    uint32_t bits = o0 ^ o1;
    float u = __uint_as_float((bits >> 9) | 0x3F800000u) - 1.0f;
    return (u >= 0.3f) ? (h / 0.7f) : 0.0f;
}

// load 8 consecutive halfs (16B, one LDG.128) -> 8 floats
__device__ __forceinline__ void ld_h8(const __half* p, float* f)
{
    uint4 r = *(const uint4*)p;
    __half2 h0 = *(__half2*)&r.x, h1 = *(__half2*)&r.y,
            h2 = *(__half2*)&r.z, h3 = *(__half2*)&r.w;
    float2 f0 = __half22float2(h0), f1 = __half22float2(h1),
           f2 = __half22float2(h2), f3 = __half22float2(h3);
    f[0] = f0.x; f[1] = f0.y; f[2] = f1.x; f[3] = f1.y;
    f[4] = f2.x; f[5] = f2.y; f[6] = f3.x; f[7] = f3.y;
}

// ---------------- CSR build ----------------
__global__ void k_hist(const int4* __restrict__ dst4)
{
    unsigned i = blockIdx.x * blockDim.x + threadIdx.x;   // grid covers NE/4 exactly
    int4 d = dst4[i];
    atomicAdd(&g_cnt[d.x], 1);
    atomicAdd(&g_cnt[d.y], 1);
    atomicAdd(&g_cnt[d.z], 1);
    atomicAdd(&g_cnt[d.w], 1);
}

// block-wide exclusive scan via warp shuffles (256 threads)
__global__ void k_scan1()
{
    __shared__ int wsum[8];
    unsigned t = threadIdx.x, wid = t >> 5, lane = t & 31;
    unsigned i = blockIdx.x * 256 + t;
    int v = (i < NN) ? g_cnt[i] : 0;

    int sc = v;
#pragma unroll
    for (int d = 1; d < 32; d <<= 1) {
        int o = __shfl_up_sync(0xffffffffu, sc, d);
        if (lane >= (unsigned)d) sc += o;
    }
    if (lane == 31) wsum[wid] = sc;
    __syncthreads();
    if (wid == 0 && lane < 8) {
        int w = wsum[lane];
#pragma unroll
        for (int d = 1; d < 8; d <<= 1) {
            int o = __shfl_up_sync(0x000000ffu, w, d);
            if (lane >= (unsigned)d) w += o;
        }
        wsum[lane] = w;
    }
    __syncthreads();
    int incl = sc + (wid ? wsum[wid - 1] : 0);
    if (i < NN) g_off[i] = incl - v;             // exclusive
    if (t == 255) g_bsum[blockIdx.x] = incl;     // block total
}

// single-block exclusive scan over NB1 block sums (512 threads)
__global__ void k_scan2()
{
    __shared__ int wsum[16];
    unsigned t = threadIdx.x, wid = t >> 5, lane = t & 31;
    int v = (t < NB1) ? g_bsum[t] : 0;

    int sc = v;
#pragma unroll
    for (int d = 1; d < 32; d <<= 1) {
        int o = __shfl_up_sync(0xffffffffu, sc, d);
        if (lane >= (unsigned)d) sc += o;
    }
    if (lane == 31) wsum[wid] = sc;
    __syncthreads();
    if (wid == 0 && lane < 16) {
        int w = wsum[lane];
#pragma unroll
        for (int d = 1; d < 16; d <<= 1) {
            int o = __shfl_up_sync(0x0000ffffu, w, d);
            if (lane >= (unsigned)d) w += o;
        }
        wsum[lane] = w;
    }
    __syncthreads();
    int incl = sc + (wid ? wsum[wid - 1] : 0);
    g_bsum[t] = incl - v;                        // exclusive block offsets
}

// finalize offsets/cursors/dinv, then re-zero cnt for the next replay
__global__ void k_scan3()
{
    unsigned i = blockIdx.x * blockDim.x + threadIdx.x;
    if (i < NN) {
        int o = g_off[i] + g_bsum[i >> 8];
        g_off[i] = o;
        g_cur[i] = o;
        g_dinv[i] = rsqrtf((float)(g_cnt[i] + 1));   // +1 self-loop
        g_cnt[i] = 0;                                // replay invariant
    }
}

__global__ void k_fill(const int4* __restrict__ src4, const int4* __restrict__ dst4)
{
    unsigned i = blockIdx.x * blockDim.x + threadIdx.x;   // grid covers NE/4 exactly
    int4 s = src4[i];
    int4 d = dst4[i];
    g_csrc[atomicAdd(&g_cur[d.x], 1)] = s.x;
    g_csrc[atomicAdd(&g_cur[d.y], 1)] = s.y;
    g_csrc[atomicAdd(&g_cur[d.z], 1)] = s.z;
    g_csrc[atomicAdd(&g_cur[d.w], 1)] = s.w;
}

// ---------------- LayerNorm + GEMM1 (warp per node), pipelined, dinv-prescaled fp16 out ----------------
__global__ __launch_bounds__(256, 2) void k_ln_gemm(
    const float* __restrict__ x,
    const float* __restrict__ gamma, const float* __restrict__ beta,
    const float* __restrict__ W1)
{
    unsigned l = threadIdx.x & 31;
    unsigned warp = blockIdx.x * (blockDim.x >> 5) + (threadIdx.x >> 5);
    unsigned nwarps = gridDim.x * (blockDim.x >> 5);

    float4 g4 = *(const float4*)(gamma + l * 4);
    float4 b4 = *(const float4*)(beta + l * 4);
    float4 w[16];
#pragma unroll
    for (int c = 0; c < 4; ++c)
#pragma unroll
        for (int q = 0; q < 4; ++q)
            w[c * 4 + q] = *(const float4*)(W1 + (size_t)(l * 4 + c) * 16 + q * 4);

    unsigned n = warp;
    float4 xv = make_float4(0.f, 0.f, 0.f, 0.f);
    float di = 0.f;
    if (n < NN) {
        xv = *(const float4*)(x + (size_t)n * DIN + l * 4);
        di = g_dinv[n];
    }

    while (n < NN) {
        unsigned n2 = n + nwarps;                 // prefetch next node
        float4 xv2 = make_float4(0.f, 0.f, 0.f, 0.f);
        float di2 = 0.f;
        if (n2 < NN) {
            xv2 = *(const float4*)(x + (size_t)n2 * DIN + l * 4);
            di2 = g_dinv[n2];
        }

        float s  = xv.x + xv.y + xv.z + xv.w;
        float ss = xv.x * xv.x + xv.y * xv.y + xv.z * xv.z + xv.w * xv.w;
#pragma unroll
        for (int d = 16; d >= 1; d >>= 1) {
            s  += __shfl_xor_sync(0xffffffffu, s,  d);
            ss += __shfl_xor_sync(0xffffffffu, ss, d);
        }
        float mu  = s * (1.0f / 128.0f);
        float var = ss * (1.0f / 128.0f) - mu * mu;
        float rs  = rsqrtf(var + 1e-5f);

        float xn[4];
        xn[0] = (xv.x - mu) * rs * g4.x + b4.x;
        xn[1] = (xv.y - mu) * rs * g4.y + b4.y;
        xn[2] = (xv.z - mu) * rs * g4.z + b4.z;
        xn[3] = (xv.w - mu) * rs * g4.w + b4.w;

        float p[16];
#pragma unroll
        for (int j = 0; j < 16; ++j) p[j] = 0.0f;
#pragma unroll
        for (int c = 0; c < 4; ++c) {
#pragma unroll
            for (int q = 0; q < 4; ++q) {
                p[q * 4 + 0] = fmaf(xn[c], w[c * 4 + q].x, p[q * 4 + 0]);
                p[q * 4 + 1] = fmaf(xn[c], w[c * 4 + q].y, p[q * 4 + 1]);
                p[q * 4 + 2] = fmaf(xn[c], w[c * 4 + q].z, p[q * 4 + 2]);
                p[q * 4 + 3] = fmaf(xn[c], w[c * 4 + q].w, p[q * 4 + 3]);
            }
        }
        {
            bool hi;
#define RED_STEP(D, M)                                                        \
            hi = (l & D) != 0;                                                \
            _Pragma("unroll")                                                 \
            for (int i = 0; i < M; ++i) {                                     \
                float send  = hi ? p[i] : p[i + M];                           \
                float other = __shfl_xor_sync(0xffffffffu, send, D);          \
                float keep  = hi ? p[i + M] : p[i];                           \
                p[i] = keep + other;                                          \
            }
            RED_STEP(16, 8) RED_STEP(8, 4) RED_STEP(4, 2) RED_STEP(2, 1)
#undef RED_STEP
            p[0] += __shfl_xor_sync(0xffffffffu, p[0], 1);
        }
        // all lanes hold feature (l>>1); pack fp16 pairs on lanes with l%4==0
        {
            float val = p[0] * di;
            float vnx = __shfl_down_sync(0xffffffffu, val, 2);
            if ((l & 3) == 0)
                *(__half2*)(g_h1 + (size_t)n * 16 + (l >> 1)) = __floats2half2_rn(val, vnx);
        }

        n = n2; xv = xv2; di = di2;
    }
}

// ---------------- fused CSR gather + epilogue: warp per dst node ----------------
// pass=0: gather g_h1, epilogue = relu/dropout(dk1)/@W2/prescale -> fp16 g_t
// pass=1: gather g_t,  epilogue = relu/dropout(dk2)              -> fp32 out
__global__ __launch_bounds__(256) void k_gather(
    int pass, const float* __restrict__ bvec, const float* __restrict__ W2,
    float* __restrict__ out, uint32_t k0, uint32_t k1)
{
    __shared__ float w2s[256];
    __shared__ float rows[8][16];

    unsigned tid = threadIdx.x;
    if (pass == 0) w2s[tid] = W2[tid];

    const __half* __restrict__ h = pass ? g_t : g_h1;

    unsigned wslot = tid >> 5;
    unsigned n = blockIdx.x * 8 + wslot;   // 12500 * 8 = 100000 exactly
    unsigned l = tid & 31;
    unsigned g = l >> 1, c = l & 1;        // 16 edge-groups, 2 lanes each
    int end = g_cur[n];
    int e = g_off[n] + (int)g;

    float a[8], b[8];
#pragma unroll
    for (int i = 0; i < 8; ++i) { a[i] = 0.f; b[i] = 0.f; }

    for (; e + 16 < end; e += 32) {        // 32 edges in flight per warp
        int s0 = __ldg(&g_csrc[e]);
        int s1 = __ldg(&g_csrc[e + 16]);
        float f0[8], f1[8];
        ld_h8(h + (size_t)s0 * 16 + c * 8, f0);
        ld_h8(h + (size_t)s1 * 16 + c * 8, f1);
#pragma unroll
        for (int i = 0; i < 8; ++i) { a[i] += f0[i]; b[i] += f1[i]; }
    }
    if (e < end) {                          // at most one tail slot
        int s = __ldg(&g_csrc[e]);
        float f0[8];
        ld_h8(h + (size_t)s * 16 + c * 8, f0);
#pragma unroll
        for (int i = 0; i < 8; ++i) a[i] += f0[i];
    }
#pragma unroll
    for (int i = 0; i < 8; ++i) a[i] += b[i];

#pragma unroll
    for (int d = 2; d < 32; d <<= 1)
#pragma unroll
        for (int i = 0; i < 8; ++i)
            a[i] += __shfl_xor_sync(0xffffffffu, a[i], d);
    // now every even lane holds features 0-7, every odd lane features 8-15

    if (l < 2) {
#pragma unroll
        for (int i = 0; i < 8; ++i) rows[wslot][c * 8 + i] = a[i];
    }
    __syncwarp();

    // epilogue on lanes 0-15: one feature each
    if (l < 16) {
        float di = g_dinv[n];
        float self = __half2float(h[(size_t)n * 16 + l]);
        float sum = rows[wslot][l] + self;
        float v = fmaxf(fmaf(di, sum, bvec[l]), 0.0f);
        v = dropout_elem(v, k0, k1, n * 16 + l);

        if (pass == 0) {
            float acc = 0.0f;
#pragma unroll
            for (int jj = 0; jj < 16; ++jj) {
                float hv = __shfl_sync(0x0000ffffu, v, jj, 16);
                acc = fmaf(hv, w2s[jj * 16 + l], acc);
            }
            acc *= di;
            float acc2 = __shfl_down_sync(0x0000ffffu, acc, 1);
            if (!(l & 1))
                *(__half2*)(g_t + (size_t)n * 16 + l) = __floats2half2_rn(acc, acc2);
        } else {
            out[(size_t)n * 16 + l] = v;
        }
    }
}

// ---------------- launch ----------------
extern "C" void kernel_launch(void* const* d_in, const int* in_sizes, int n_in,
                              void* d_out, int out_size)
{
    const float* x     = (const float*)d_in[0];
    const int*   ei    = (const int*)d_in[1];
    const float* gamma = (const float*)d_in[2];
    const float* beta  = (const float*)d_in[3];
    const float* W1    = (const float*)d_in[4];
    const float* b1    = (const float*)d_in[5];
    const float* W2    = (const float*)d_in[6];
    const float* b2    = (const float*)d_in[7];
    float* out = (float*)d_out;

    const int4* src4 = (const int4*)ei;            // edge_index[0]
    const int4* dst4 = (const int4*)(ei + NE);     // edge_index[1]

    // JAX partitionable split: dk1 = threefry(key,(0,0)), dk2 = threefry(key,(0,1))
    uint32_t A0, A1, B0, B1;
    threefry2x32(0u, 42u, 0u, 0u, A0, A1);
    threefry2x32(0u, 42u, 0u, 1u, B0, B1);

    k_hist<<<NE / 4 / 256, 256>>>(dst4);
    k_scan1<<<NB1, 256>>>();
    k_scan2<<<1, 512>>>();
    k_scan3<<<NB1, 256>>>();
    k_fill<<<NE / 4 / 256, 256>>>(src4, dst4);
    k_ln_gemm<<<592, 256>>>(x, gamma, beta, W1);
    k_gather<<<12500, 256>>>(0, b1, W2, out, A0, A1);
    k_gather<<<12500, 256>>>(1, b2, W2, out, B0, B1);
}

// round 11
// speedup vs baseline: 1.0636x; 1.0636x over previous
#include <cuda_runtime.h>
#include <cuda_fp16.h>
#include <cstdint>

#define NN 100000
#define NE 6400000
#define DIN 128
#define HID 16
#define TOT (NN * HID)
#define NB1 391            // ceil(NN/256)

// ---------------- scratch (static device globals; no allocation) ----------------
__device__ __align__(16) __half g_h1[TOT];   // fp16: dinv[n] * (xn @ W1)
__device__ __align__(16) __half g_t[TOT];    // fp16: dinv[n] * (dropout(relu(conv1)) @ W2)
__device__ __align__(16) float  g_a1[TOT];   // conv1 gather sums (fp32)
__device__ __align__(16) float  g_a2[TOT];   // conv2 gather sums (fp32)
__device__ float g_dinv[NN];
__device__ int   g_cnt[NN];                  // in-degree (excl self-loop); re-zeroed each replay
__device__ int   g_off[NN];                  // CSR row start; after fill = row END
__device__ int   g_bsum[512];                // block sums for scan
__device__ int   g_csrc[NE];                 // CSR: src per slot

// ---------------- JAX Threefry-2x32 (20 rounds), bit-exact ----------------
__host__ __device__ __forceinline__ void threefry2x32(
    uint32_t k0, uint32_t k1, uint32_t x0, uint32_t x1,
    uint32_t& o0, uint32_t& o1)
{
    uint32_t ks2 = k0 ^ k1 ^ 0x1BD11BDAu;
    x0 += k0; x1 += k1;
#define TF_R(r) { x0 += x1; x1 = (x1 << r) | (x1 >> (32 - r)); x1 ^= x0; }
    TF_R(13) TF_R(15) TF_R(26) TF_R(6)
    x0 += k1;  x1 += ks2 + 1u;
    TF_R(17) TF_R(29) TF_R(16) TF_R(24)
    x0 += ks2; x1 += k0 + 2u;
    TF_R(13) TF_R(15) TF_R(26) TF_R(6)
    x0 += k0;  x1 += k1 + 3u;
    TF_R(17) TF_R(29) TF_R(16) TF_R(24)
    x0 += k1;  x1 += ks2 + 4u;
    TF_R(13) TF_R(15) TF_R(26) TF_R(6)
    x0 += ks2; x1 += k0 + 5u;
#undef TF_R
    o0 = x0; o1 = x1;
}

// Partitionable-mode random_bits: counter (0, i); output = o0 ^ o1.
__device__ __forceinline__ float dropout_elem(float h, uint32_t k0, uint32_t k1, uint32_t i)
{
    uint32_t o0, o1;
    threefry2x32(k0, k1, 0u, i, o0, o1);
    uint32_t bits = o0 ^ o1;
    float u = __uint_as_float((bits >> 9) | 0x3F800000u) - 1.0f;
    return (u >= 0.3f) ? (h / 0.7f) : 0.0f;
}

// load 4 consecutive halfs (8B) -> float4
__device__ __forceinline__ float4 ld_h4(const __half* p)
{
    uint2 r = *(const uint2*)p;
    __half2 h0 = *(__half2*)&r.x, h1 = *(__half2*)&r.y;
    float2 f0 = __half22float2(h0), f1 = __half22float2(h1);
    return make_float4(f0.x, f0.y, f1.x, f1.y);
}

// ---------------- CSR build ----------------
__global__ void k_hist(const int4* __restrict__ dst4)
{
    unsigned i = blockIdx.x * blockDim.x + threadIdx.x;   // grid covers NE/4 exactly
    int4 d = dst4[i];
    atomicAdd(&g_cnt[d.x], 1);
    atomicAdd(&g_cnt[d.y], 1);
    atomicAdd(&g_cnt[d.z], 1);
    atomicAdd(&g_cnt[d.w], 1);
}

// block-wide exclusive scan via warp shuffles (256 threads)
__global__ void k_scan1()
{
    __shared__ int wsum[8];
    unsigned t = threadIdx.x, wid = t >> 5, lane = t & 31;
    unsigned i = blockIdx.x * 256 + t;
    int v = (i < NN) ? g_cnt[i] : 0;

    int sc = v;
#pragma unroll
    for (int d = 1; d < 32; d <<= 1) {
        int o = __shfl_up_sync(0xffffffffu, sc, d);
        if (lane >= (unsigned)d) sc += o;
    }
    if (lane == 31) wsum[wid] = sc;
    __syncthreads();
    if (wid == 0 && lane < 8) {
        int w = wsum[lane];
#pragma unroll
        for (int d = 1; d < 8; d <<= 1) {
            int o = __shfl_up_sync(0x000000ffu, w, d);
            if (lane >= (unsigned)d) w += o;
        }
        wsum[lane] = w;
    }
    __syncthreads();
    int incl = sc + (wid ? wsum[wid - 1] : 0);
    if (i < NN) g_off[i] = incl - v;             // exclusive
    if (t == 255) g_bsum[blockIdx.x] = incl;     // block total
}

// single-block exclusive scan over NB1 block sums (512 threads)
__global__ void k_scan2()
{
    __shared__ int wsum[16];
    unsigned t = threadIdx.x, wid = t >> 5, lane = t & 31;
    int v = (t < NB1) ? g_bsum[t] : 0;

    int sc = v;
#pragma unroll
    for (int d = 1; d < 32; d <<= 1) {
        int o = __shfl_up_sync(0xffffffffu, sc, d);
        if (lane >= (unsigned)d) sc += o;
    }
    if (lane == 31) wsum[wid] = sc;
    __syncthreads();
    if (wid == 0 && lane < 16) {
        int w = wsum[lane];
#pragma unroll
        for (int d = 1; d < 16; d <<= 1) {
            int o = __shfl_up_sync(0x0000ffffu, w, d);
            if (lane >= (unsigned)d) w += o;
        }
        wsum[lane] = w;
    }
    __syncthreads();
    int incl = sc + (wid ? wsum[wid - 1] : 0);
    g_bsum[t] = incl - v;                        // exclusive block offsets
}

// finalize offsets/dinv, then re-zero cnt for the next replay
__global__ void k_scan3()
{
    unsigned i = blockIdx.x * blockDim.x + threadIdx.x;
    if (i < NN) {
        g_off[i] = g_off[i] + g_bsum[i >> 8];
        g_dinv[i] = rsqrtf((float)(g_cnt[i] + 1));   // +1 self-loop
        g_cnt[i] = 0;                                // replay invariant
    }
}

// cursors advance directly on g_off; after fill, g_off[n] = end of row n
__global__ void k_fill(const int4* __restrict__ src4, const int4* __restrict__ dst4)
{
    unsigned i = blockIdx.x * blockDim.x + threadIdx.x;   // grid covers NE/4 exactly
    int4 s = src4[i];
    int4 d = dst4[i];
    g_csrc[atomicAdd(&g_off[d.x], 1)] = s.x;
    g_csrc[atomicAdd(&g_off[d.y], 1)] = s.y;
    g_csrc[atomicAdd(&g_off[d.z], 1)] = s.z;
    g_csrc[atomicAdd(&g_off[d.w], 1)] = s.w;
}

// ---------------- LayerNorm + GEMM1 (warp per node), fp16 W cache, dinv-prescaled fp16 out --------
__global__ __launch_bounds__(256, 3) void k_ln_gemm(
    const float* __restrict__ x,
    const float* __restrict__ gamma, const float* __restrict__ beta,
    const float* __restrict__ W1)
{
    unsigned l = threadIdx.x & 31;
    unsigned warp = blockIdx.x * (blockDim.x >> 5) + (threadIdx.x >> 5);
    unsigned nwarps = gridDim.x * (blockDim.x >> 5);

    float4 g4 = *(const float4*)(gamma + l * 4);
    float4 b4 = *(const float4*)(beta + l * 4);
    // W1 rows 4l..4l+3 cached as fp16 (32 regs instead of 64)
    __half2 w[32];
#pragma unroll
    for (int c = 0; c < 4; ++c)
#pragma unroll
        for (int q = 0; q < 4; ++q) {
            float4 wv = *(const float4*)(W1 + (size_t)(l * 4 + c) * 16 + q * 4);
            w[(c * 4 + q) * 2 + 0] = __floats2half2_rn(wv.x, wv.y);
            w[(c * 4 + q) * 2 + 1] = __floats2half2_rn(wv.z, wv.w);
        }

    unsigned n = warp;
    float4 xv = make_float4(0.f, 0.f, 0.f, 0.f);
    float di = 0.f;
    if (n < NN) {
        xv = *(const float4*)(x + (size_t)n * DIN + l * 4);
        di = g_dinv[n];
    }

    while (n < NN) {
        unsigned n2 = n + nwarps;                 // prefetch next node
        float4 xv2 = make_float4(0.f, 0.f, 0.f, 0.f);
        float di2 = 0.f;
        if (n2 < NN) {
            xv2 = *(const float4*)(x + (size_t)n2 * DIN + l * 4);
            di2 = g_dinv[n2];
        }

        float s  = xv.x + xv.y + xv.z + xv.w;
        float ss = xv.x * xv.x + xv.y * xv.y + xv.z * xv.z + xv.w * xv.w;
#pragma unroll
        for (int d = 16; d >= 1; d >>= 1) {
            s  += __shfl_xor_sync(0xffffffffu, s,  d);
            ss += __shfl_xor_sync(0xffffffffu, ss, d);
        }
        float mu  = s * (1.0f / 128.0f);
        float var = ss * (1.0f / 128.0f) - mu * mu;
        float rs  = rsqrtf(var + 1e-5f);

        float xn[4];
        xn[0] = (xv.x - mu) * rs * g4.x + b4.x;
        xn[1] = (xv.y - mu) * rs * g4.y + b4.y;
        xn[2] = (xv.z - mu) * rs * g4.z + b4.z;
        xn[3] = (xv.w - mu) * rs * g4.w + b4.w;

        float p[16];
#pragma unroll
        for (int j = 0; j < 16; ++j) p[j] = 0.0f;
#pragma unroll
        for (int c = 0; c < 4; ++c) {
#pragma unroll
            for (int q = 0; q < 4; ++q) {
                float2 wa = __half22float2(w[(c * 4 + q) * 2 + 0]);
                float2 wb = __half22float2(w[(c * 4 + q) * 2 + 1]);
                p[q * 4 + 0] = fmaf(xn[c], wa.x, p[q * 4 + 0]);
                p[q * 4 + 1] = fmaf(xn[c], wa.y, p[q * 4 + 1]);
                p[q * 4 + 2] = fmaf(xn[c], wb.x, p[q * 4 + 2]);
                p[q * 4 + 3] = fmaf(xn[c], wb.y, p[q * 4 + 3]);
            }
        }
        {
            bool hi;
#define RED_STEP(D, M)                                                        \
            hi = (l & D) != 0;                                                \
            _Pragma("unroll")                                                 \
            for (int i = 0; i < M; ++i) {                                     \
                float send  = hi ? p[i] : p[i + M];                           \
                float other = __shfl_xor_sync(0xffffffffu, send, D);          \
                float keep  = hi ? p[i + M] : p[i];                           \
                p[i] = keep + other;                                          \
            }
            RED_STEP(16, 8) RED_STEP(8, 4) RED_STEP(4, 2) RED_STEP(2, 1)
#undef RED_STEP
            p[0] += __shfl_xor_sync(0xffffffffu, p[0], 1);
        }
        // all lanes hold feature (l>>1); pack fp16 pairs on lanes with l%4==0
        {
            float val = p[0] * di;
            float vnx = __shfl_down_sync(0xffffffffu, val, 2);
            if ((l & 3) == 0)
                *(__half2*)(g_h1 + (size_t)n * 16 + (l >> 1)) = __floats2half2_rn(val, vnx);
        }

        n = n2; xv = xv2; di = di2;
    }
}

// ---------------- CSR gather (fp16 h): warp per dst node, 4 lanes/edge, 4x unroll ----------------
// pass=0: h=g_h1 acc=g_a1 ; pass=1: h=g_t acc=g_a2 (selected DEVICE-side)
__global__ __launch_bounds__(256) void k_gather(int pass)
{
    const __half* __restrict__ h = pass ? g_t : g_h1;
    float* __restrict__ acc      = pass ? g_a2 : g_a1;

    unsigned n = blockIdx.x * 8 + (threadIdx.x >> 5);   // 12500 * 8 = 100000 exactly
    unsigned l = threadIdx.x & 31;
    unsigned g = l >> 2, c = l & 3;
    int beg = n ? g_off[n - 1] : 0;                     // row start = prev row end
    int end = g_off[n];
    int e = beg + (int)g;

    float4 a0 = make_float4(0.f, 0.f, 0.f, 0.f);
    float4 a1 = make_float4(0.f, 0.f, 0.f, 0.f);
    float4 a2 = make_float4(0.f, 0.f, 0.f, 0.f);
    float4 a3 = make_float4(0.f, 0.f, 0.f, 0.f);
    for (; e + 24 < end; e += 32) {                // four edges in flight per group
        int s0 = __ldg(&g_csrc[e]);
        int s1 = __ldg(&g_csrc[e + 8]);
        int s2 = __ldg(&g_csrc[e + 16]);
        int s3 = __ldg(&g_csrc[e + 24]);
        float4 h0 = ld_h4(h + (size_t)s0 * 16 + c * 4);
        float4 h1 = ld_h4(h + (size_t)s1 * 16 + c * 4);
        float4 h2 = ld_h4(h + (size_t)s2 * 16 + c * 4);
        float4 h3 = ld_h4(h + (size_t)s3 * 16 + c * 4);
        a0.x += h0.x; a0.y += h0.y; a0.z += h0.z; a0.w += h0.w;
        a1.x += h1.x; a1.y += h1.y; a1.z += h1.z; a1.w += h1.w;
        a2.x += h2.x; a2.y += h2.y; a2.z += h2.z; a2.w += h2.w;
        a3.x += h3.x; a3.y += h3.y; a3.z += h3.z; a3.w += h3.w;
    }
    for (; e < end; e += 8) {
        int s = __ldg(&g_csrc[e]);
        float4 hv = ld_h4(h + (size_t)s * 16 + c * 4);
        a0.x += hv.x; a0.y += hv.y; a0.z += hv.z; a0.w += hv.w;
    }
    a0.x += a1.x + a2.x + a3.x;
    a0.y += a1.y + a2.y + a3.y;
    a0.z += a1.z + a2.z + a3.z;
    a0.w += a1.w + a2.w + a3.w;

#pragma unroll
    for (int d = 4; d < 32; d <<= 1) {
        a0.x += __shfl_xor_sync(0xffffffffu, a0.x, d);
        a0.y += __shfl_xor_sync(0xffffffffu, a0.y, d);
        a0.z += __shfl_xor_sync(0xffffffffu, a0.z, d);
        a0.w += __shfl_xor_sync(0xffffffffu, a0.w, d);
    }
    if (l < 4) {
        float4 hv = ld_h4(h + (size_t)n * 16 + c * 4);   // self-loop
        a0.x += hv.x; a0.y += hv.y; a0.z += hv.z; a0.w += hv.w;
        *(float4*)(acc + (size_t)n * 16 + c * 4) = a0;
    }
}

// ---------------- post conv1: dinv*sum + b1, relu, dropout(dk1), @W2, prescale, fp16 out ----------------
__global__ void k_post1(const float* __restrict__ b1, const float* __restrict__ W2,
                        uint32_t k0, uint32_t k1)
{
    __shared__ float w2s[256];
    unsigned tid = threadIdx.x;
    w2s[tid] = W2[tid];
    __syncthreads();

    unsigned idx = blockIdx.x * blockDim.x + tid;   // grid covers TOT exactly
    unsigned n = idx >> 4, j = idx & 15;
    float di = g_dinv[n];
    float v = fmaxf(fmaf(di, g_a1[idx], b1[j]), 0.0f);
    v = dropout_elem(v, k0, k1, idx);

    float acc = 0.0f;
#pragma unroll
    for (int jj = 0; jj < 16; ++jj) {
        float hv = __shfl_sync(0xffffffffu, v, jj, 16);
        acc = fmaf(hv, w2s[jj * 16 + j], acc);
    }
    acc *= di;
    float acc2 = __shfl_down_sync(0xffffffffu, acc, 1);
    if (!(j & 1))
        *(__half2*)(g_t + (size_t)n * 16 + j) = __floats2half2_rn(acc, acc2);
}

// ---------------- final: dinv*sum + b2, relu, dropout(dk2) -> out ----------------
__global__ void k_final(float* __restrict__ out, const float* __restrict__ b2,
                        uint32_t k0, uint32_t k1)
{
    unsigned idx = blockIdx.x * blockDim.x + threadIdx.x;   // covers TOT exactly
    unsigned n = idx >> 4, j = idx & 15;
    float v = fmaxf(fmaf(g_dinv[n], g_a2[idx], b2[j]), 0.0f);
    out[idx] = dropout_elem(v, k0, k1, idx);
}

// ---------------- launch ----------------
extern "C" void kernel_launch(void* const* d_in, const int* in_sizes, int n_in,
                              void* d_out, int out_size)
{
    const float* x     = (const float*)d_in[0];
    const int*   ei    = (const int*)d_in[1];
    const float* gamma = (const float*)d_in[2];
    const float* beta  = (const float*)d_in[3];
    const float* W1    = (const float*)d_in[4];
    const float* b1    = (const float*)d_in[5];
    const float* W2    = (const float*)d_in[6];
    const float* b2    = (const float*)d_in[7];
    float* out = (float*)d_out;

    const int4* src4 = (const int4*)ei;            // edge_index[0]
    const int4* dst4 = (const int4*)(ei + NE);     // edge_index[1]

    // JAX partitionable split: dk1 = threefry(key,(0,0)), dk2 = threefry(key,(0,1))
    uint32_t A0, A1, B0, B1;
    threefry2x32(0u, 42u, 0u, 0u, A0, A1);
    threefry2x32(0u, 42u, 0u, 1u, B0, B1);

    k_hist<<<NE / 4 / 256, 256>>>(dst4);
    k_scan1<<<NB1, 256>>>();
    k_scan2<<<1, 512>>>();
    k_scan3<<<NB1, 256>>>();
    k_fill<<<NE / 4 / 256, 256>>>(src4, dst4);
    k_ln_gemm<<<444, 256>>>(x, gamma, beta, W1);
    k_gather<<<12500, 256>>>(0);
    k_post1<<<TOT / 256, 256>>>(b1, W2, A0, A1);
    k_gather<<<12500, 256>>>(1);
    k_final<<<TOT / 256, 256>>>(out, b2, B0, B1);
}